// round 8
// baseline (speedup 1.0000x reference)
#include <cuda_runtime.h>
#include <math.h>

// ToneStack: 3 cascaded low-shelf biquads over x:[64, 480000] fp32.
// SINGLE-PASS fused kernel with decoupled lookback:
//   each block owns 125 chunks (128 samples each) staged once in smem;
//   phase A: per-chunk zero-state finals via weighted reduction
//   phase B: in-block scan -> block aggregate F, publish (fence+flag)
//   phase C: lookback over <=29 same-row predecessors with Tb^p powers
//   phase D: seeded in-block scan -> per-chunk entry states
//   phase E: serial re-filter from smem, coalesced store of y.
// x is read from DRAM exactly once (123 MB read + 123 MB write total).

#define TLEN    480000
#define NROW    64
#define CHUNK   128
#define CROW    3750             // chunks per row
#define BCHUNK  125              // chunks per block
#define BROW    30               // blocks per row
#define GRID    (NROW * BROW)    // 1920
#define SPAN    (BCHUNK * CHUNK) // 16000 floats per block
#define RSTRIDE 132              // smem row stride in words (4-aligned, cf-free)
#define TILE_SMEM (BCHUNK * RSTRIDE * 4)

__device__ float g_coef[15];        // per stage: b0, c1, c2, -a1, -a2
__device__ float g_T[36];           // A^CHUNK
__device__ float g_T5[36];          // T^5
__device__ float g_Tbp[30 * 36];    // (T^125)^p, p = 0..29
__device__ float g_W6[6][CHUNK];    // transposed reduction weights
__device__ float g_F[GRID * 6];     // block aggregates
__device__ int   g_flag[GRID];      // publication flags

// ---------------------------------------------------------------- setup ----

__device__ void shelf_coefs(double fc, double gdb, double Q, double* out) {
    const double PI = 3.14159265358979323846;
    double A  = pow(10.0, gdb / 40.0);
    double w0 = 2.0 * PI * fc / 48000.0;
    double al = sin(w0) / (2.0 * Q);
    double cw = cos(w0);
    double sq = sqrt(A);
    double b0 = A * ((A + 1.0) - (A - 1.0) * cw + 2.0 * sq * al);
    double b1 = 2.0 * A * ((A - 1.0) - (A + 1.0) * cw);
    double b2 = A * ((A + 1.0) - (A - 1.0) * cw - 2.0 * sq * al);
    double a0 = (A + 1.0) + (A - 1.0) * cw + 2.0 * sq * al;
    double a1 = -2.0 * ((A - 1.0) + (A + 1.0) * cw);
    double a2 = (A + 1.0) + (A - 1.0) * cw - 2.0 * sq * al;
    b0 /= a0; b1 /= a0; b2 /= a0; a1 /= a0; a2 /= a0;
    out[0] = b0;
    out[1] = b1 - a1 * b0;   // c1
    out[2] = b2 - a2 * b0;   // c2
    out[3] = -a1;
    out[4] = -a2;
}

#define MATMUL(D, A_, B_)                                                     \
    do {                                                                      \
        if (tid < 36) {                                                       \
            int r_ = tid / 6, c_ = tid % 6;                                   \
            float acc_ = 0.f;                                                 \
            for (int k_ = 0; k_ < 6; k_++)                                    \
                acc_ += (A_)[r_ * 6 + k_] * (B_)[k_ * 6 + c_];                \
            (D)[tid] = acc_;                                                  \
        }                                                                     \
        __syncthreads();                                                      \
    } while (0)

__global__ void setup_kernel(const float* lg, const float* mg, const float* mfc,
                             const float* mq, const float* hg) {
    __shared__ double scoef[15];
    __shared__ double db[6];
    __shared__ float sP[7][36];   // A^(2^k)
    __shared__ float sQ[7][36];   // T^(2^k)
    __shared__ float M0[36], M1[36], M2[36], M3[36], M4[36];
    int tid = threadIdx.x;

    // reset flags for this replay
    for (int i = tid; i < GRID; i += 256) g_flag[i] = 0;

    if (tid == 0) {
        double c[5];
        shelf_coefs(120.0, (double)*lg, (double)0.707f, c);
        for (int i = 0; i < 5; i++) { scoef[i] = c[i];      g_coef[i]      = (float)c[i]; }
        shelf_coefs((double)*mfc, (double)*mg, (double)*mq, c);
        for (int i = 0; i < 5; i++) { scoef[5 + i] = c[i];  g_coef[5 + i]  = (float)c[i]; }
        shelf_coefs(4000.0, (double)*hg, (double)0.707f, c);
        for (int i = 0; i < 5; i++) { scoef[10 + i] = c[i]; g_coef[10 + i] = (float)c[i]; }
    }
    __syncthreads();

    // one-step 6x6 matrix A
    if (tid < 6) {
        double z[6] = {0, 0, 0, 0, 0, 0};
        z[tid] = 1.0;
        double u = 0.0;
        double ns[6];
        for (int st = 0; st < 3; st++) {
            double b0  = scoef[st * 5 + 0], c1 = scoef[st * 5 + 1], c2 = scoef[st * 5 + 2];
            double na1 = scoef[st * 5 + 3], na2 = scoef[st * 5 + 4];
            double z1 = z[2 * st], z2 = z[2 * st + 1];
            double y = b0 * u + z1;
            ns[2 * st]     = c1 * u + na1 * z1 + z2;
            ns[2 * st + 1] = c2 * u + na2 * z1;
            u = y;
        }
        for (int i = 0; i < 6; i++) M0[i * 6 + tid] = (float)ns[i];
    }
    if (tid == 0) {
        double y0 = scoef[0];
        double y1 = scoef[5] * y0;
        db[0] = scoef[1];  db[1] = scoef[2];
        db[2] = scoef[6] * y0;   db[3] = scoef[7] * y0;
        db[4] = scoef[11] * y1;  db[5] = scoef[12] * y1;
    }
    __syncthreads();

    // A powers (for W) and T = A^128
    if (tid < 36) sP[0][tid] = M0[tid];
    __syncthreads();
    MATMUL(M1, M0, M0);  if (tid < 36) sP[1][tid] = M1[tid];   // A^2
    MATMUL(M0, M1, M1);  if (tid < 36) sP[2][tid] = M0[tid];   // A^4
    MATMUL(M1, M0, M0);  if (tid < 36) sP[3][tid] = M1[tid];   // A^8
    MATMUL(M0, M1, M1);  if (tid < 36) sP[4][tid] = M0[tid];   // A^16
    MATMUL(M1, M0, M0);  if (tid < 36) sP[5][tid] = M1[tid];   // A^32
    MATMUL(M0, M1, M1);  if (tid < 36) sP[6][tid] = M0[tid];   // A^64
    MATMUL(M1, M0, M0);                                        // A^128 = T
    if (tid < 36) { g_T[tid] = M1[tid]; sQ[0][tid] = M1[tid]; }
    __syncthreads();

    // T powers
    MATMUL(M0, M1, M1);  if (tid < 36) sQ[1][tid] = M0[tid];   // T^2
    MATMUL(M2, M0, M0);  if (tid < 36) sQ[2][tid] = M2[tid];   // T^4
    MATMUL(M0, M2, M2);  if (tid < 36) sQ[3][tid] = M0[tid];   // T^8
    MATMUL(M3, M0, M0);  if (tid < 36) sQ[4][tid] = M3[tid];   // T^16
    MATMUL(M0, M3, M3);  if (tid < 36) sQ[5][tid] = M0[tid];   // T^32
    MATMUL(M4, M0, M0);  if (tid < 36) sQ[6][tid] = M4[tid];   // T^64

    // T5 = T^4 * T
    MATMUL(M0, sQ[2], sQ[0]);
    if (tid < 36) g_T5[tid] = M0[tid];
    __syncthreads();

    // Tb = T^125 = T^64 * T^32 * T^16 * T^8 * T^4 * T
    MATMUL(M0, M4, sQ[5]);      // T^96
    MATMUL(M2, M0, sQ[4]);      // T^112
    MATMUL(M0, M2, sQ[3]);      // T^120
    MATMUL(M2, M0, sQ[2]);      // T^124
    MATMUL(M3, M2, sQ[0]);      // T^125 = Tb   (keep in M3)

    // Tbp[p] = Tb^p, p = 0..29
    if (tid < 36) {
        float idv = (tid % 7 == 0) ? 1.f : 0.f;
        M1[tid] = idv;
        g_Tbp[tid] = idv;
    }
    __syncthreads();
    for (int p = 1; p < 30; p++) {
        MATMUL(M2, M1, M3);
        if (tid < 36) { g_Tbp[p * 36 + tid] = M2[tid]; M1[tid] = M2[tid]; }
        __syncthreads();
    }

    // W[n] = A^(127-n) b, one thread per n (powers commute)
    if (tid < CHUNK) {
        int e = CHUNK - 1 - tid;
        float v[6];
#pragma unroll
        for (int j = 0; j < 6; j++) v[j] = (float)db[j];
#pragma unroll
        for (int k = 0; k < 7; k++) {
            if ((e >> k) & 1) {
                float nv[6];
#pragma unroll
                for (int j = 0; j < 6; j++) {
                    float acc = 0.f;
#pragma unroll
                    for (int kk = 0; kk < 6; kk++)
                        acc = fmaf(sP[k][j * 6 + kk], v[kk], acc);
                    nv[j] = acc;
                }
#pragma unroll
                for (int j = 0; j < 6; j++) v[j] = nv[j];
            }
        }
#pragma unroll
        for (int j = 0; j < 6; j++) g_W6[j][tid] = v[j];
    }
}

// ---------------------------------------------------------------- fused ----

__device__ __forceinline__ float step_all(float u, float z[6], const float k[15]) {
    float y0 = fmaf(k[0], u, z[0]);
    float t0 = fmaf(k[3], z[0], z[1]);
    z[1] = fmaf(k[2], u, k[4] * z[0]);
    z[0] = fmaf(k[1], u, t0);
    float y1 = fmaf(k[5], y0, z[2]);
    float t1 = fmaf(k[8], z[2], z[3]);
    z[3] = fmaf(k[7], y0, k[9] * z[2]);
    z[2] = fmaf(k[6], y0, t1);
    float y2 = fmaf(k[10], y1, z[4]);
    float t2 = fmaf(k[13], z[4], z[5]);
    z[5] = fmaf(k[12], y1, k[14] * z[4]);
    z[4] = fmaf(k[11], y1, t2);
    return y2;
}

__device__ __forceinline__ void affine_step(float s[6], const float fv[6],
                                            const float T[36]) {
    float ns[6];
#pragma unroll
    for (int j = 0; j < 6; j++) {
        float acc = fv[j];
#pragma unroll
        for (int kk = 0; kk < 6; kk++) acc = fmaf(T[j * 6 + kk], s[kk], acc);
        ns[j] = acc;
    }
#pragma unroll
    for (int j = 0; j < 6; j++) s[j] = ns[j];
}

__global__ __launch_bounds__(128) void fused_kernel(const float* __restrict__ x,
                                                    float* __restrict__ y) {
    extern __shared__ float tile[];          // BCHUNK * RSTRIDE words
    __shared__ float sw6[6][CHUNK];
    __shared__ float sk[15];
    __shared__ float sT[36], sT5[36];
    __shared__ float sfin[BCHUNK][6];
    __shared__ float sG[25][6];
    __shared__ float sgE[25][6];
    __shared__ float sS[6];

    int tid = threadIdx.x;
    int bid = blockIdx.x;
    int r = bid / BROW, j = bid % BROW;
    const float4* xb = (const float4*)(x + (size_t)r * TLEN + (size_t)j * SPAN);

    // stage x -> smem (coalesced; row c at word c*RSTRIDE)
    for (int i = tid; i < SPAN / 4; i += 128) {
        int c = i >> 5, s = (i & 31) * 4;
        *(float4*)&tile[c * RSTRIDE + s] = xb[i];
    }
    for (int i = tid; i < 6 * CHUNK / 4; i += 128)
        ((float4*)sw6)[i] = ((const float4*)g_W6)[i];
    if (tid < 36) { sT[tid] = g_T[tid]; sT5[tid] = g_T5[tid]; }
    if (tid < 15) sk[tid] = g_coef[tid];
    __syncthreads();

    // phase A: per-chunk zero-state final via W-reduction
    if (tid < BCHUNK) {
        const float4* row = (const float4*)&tile[tid * RSTRIDE];
        float f0 = 0.f, f1 = 0.f, f2 = 0.f, f3 = 0.f, f4 = 0.f, f5 = 0.f;
#pragma unroll
        for (int q = 0; q < CHUNK / 4; q++) {
            float4 v = row[q];
            int n = q * 4;
            float4 w0 = *(const float4*)&sw6[0][n];
            float4 w1 = *(const float4*)&sw6[1][n];
            float4 w2 = *(const float4*)&sw6[2][n];
            float4 w3 = *(const float4*)&sw6[3][n];
            float4 w4 = *(const float4*)&sw6[4][n];
            float4 w5 = *(const float4*)&sw6[5][n];
            f0 = fmaf(v.w, w0.w, fmaf(v.z, w0.z, fmaf(v.y, w0.y, fmaf(v.x, w0.x, f0))));
            f1 = fmaf(v.w, w1.w, fmaf(v.z, w1.z, fmaf(v.y, w1.y, fmaf(v.x, w1.x, f1))));
            f2 = fmaf(v.w, w2.w, fmaf(v.z, w2.z, fmaf(v.y, w2.y, fmaf(v.x, w2.x, f2))));
            f3 = fmaf(v.w, w3.w, fmaf(v.z, w3.z, fmaf(v.y, w3.y, fmaf(v.x, w3.x, f3))));
            f4 = fmaf(v.w, w4.w, fmaf(v.z, w4.z, fmaf(v.y, w4.y, fmaf(v.x, w4.x, f4))));
            f5 = fmaf(v.w, w5.w, fmaf(v.z, w5.z, fmaf(v.y, w5.y, fmaf(v.x, w5.x, f5))));
        }
        sfin[tid][0] = f0; sfin[tid][1] = f1; sfin[tid][2] = f2;
        sfin[tid][3] = f3; sfin[tid][4] = f4; sfin[tid][5] = f5;
    }
    __syncthreads();

    // phase B1: group aggregates (25 groups of 5 chunks), zero entry
    if (tid < 25) {
        float s[6] = {0, 0, 0, 0, 0, 0};
        for (int i = 0; i < 5; i++) affine_step(s, sfin[tid * 5 + i], sT);
#pragma unroll
        for (int z = 0; z < 6; z++) sG[tid][z] = s[z];
    }
    __syncthreads();

    // phase B2: block aggregate, publish
    if (tid == 0) {
        float s[6] = {0, 0, 0, 0, 0, 0};
        for (int g = 0; g < 25; g++) affine_step(s, sG[g], sT5);
#pragma unroll
        for (int z = 0; z < 6; z++) __stcg(&g_F[bid * 6 + z], s[z]);
        __threadfence();
        atomicExch(&g_flag[bid], 1);
    }

    // phase C: lookback over same-row predecessors (warp 0)
    if (tid < 32) {
        float acc[6] = {0, 0, 0, 0, 0, 0};
        if (tid < j) {
            int q = bid - 1 - tid;            // predecessor; power = tid
            while (atomicAdd(&g_flag[q], 0) == 0) __nanosleep(40);
            __threadfence();
            float Fv[6];
#pragma unroll
            for (int z = 0; z < 6; z++) Fv[z] = __ldcg(&g_F[q * 6 + z]);
            const float* P = &g_Tbp[tid * 36];
#pragma unroll
            for (int z = 0; z < 6; z++) {
                float a = 0.f;
#pragma unroll
                for (int kk = 0; kk < 6; kk++) a = fmaf(P[z * 6 + kk], Fv[kk], a);
                acc[z] = a;
            }
        }
#pragma unroll
        for (int o = 16; o > 0; o >>= 1)
#pragma unroll
            for (int z = 0; z < 6; z++)
                acc[z] += __shfl_down_sync(0xFFFFFFFFu, acc[z], o);
        if (tid == 0) {
#pragma unroll
            for (int z = 0; z < 6; z++) sS[z] = acc[z];
        }
    }
    __syncthreads();

    // phase D1: seeded serial scan -> group entry states
    if (tid == 0) {
        float s[6];
#pragma unroll
        for (int z = 0; z < 6; z++) s[z] = sS[z];
        for (int g = 0; g < 25; g++) {
#pragma unroll
            for (int z = 0; z < 6; z++) sgE[g][z] = s[z];
            affine_step(s, sG[g], sT5);
        }
    }
    __syncthreads();

    // phase D2 + E: per-chunk entry, serial filter, write back to smem
    if (tid < BCHUNK) {
        int g = tid / 5, o = tid % 5;
        float s[6];
#pragma unroll
        for (int z = 0; z < 6; z++) s[z] = sgE[g][z];
        for (int i = 0; i < o; i++) affine_step(s, sfin[g * 5 + i], sT);

        float k[15];
#pragma unroll
        for (int i = 0; i < 15; i++) k[i] = sk[i];
        float4* row = (float4*)&tile[tid * RSTRIDE];
#pragma unroll 8
        for (int q = 0; q < CHUNK / 4; q++) {
            float4 v = row[q];
            float4 ov;
            ov.x = step_all(v.x, s, k);
            ov.y = step_all(v.y, s, k);
            ov.z = step_all(v.z, s, k);
            ov.w = step_all(v.w, s, k);
            row[q] = ov;
        }
    }
    __syncthreads();

    // store y (coalesced)
    float4* yb = (float4*)(y + (size_t)r * TLEN + (size_t)j * SPAN);
    for (int i = tid; i < SPAN / 4; i += 128) {
        int c = i >> 5, s = (i & 31) * 4;
        yb[i] = *(const float4*)&tile[c * RSTRIDE + s];
    }
}

// ----------------------------------------------------------------- launch --

extern "C" void kernel_launch(void* const* d_in, const int* in_sizes, int n_in,
                              void* d_out, int out_size) {
    const float* x   = (const float*)d_in[0];
    const float* lg  = (const float*)d_in[1];
    const float* mg  = (const float*)d_in[2];
    const float* mfc = (const float*)d_in[3];
    const float* mq  = (const float*)d_in[4];
    const float* hg  = (const float*)d_in[5];
    float* y = (float*)d_out;

    cudaFuncSetAttribute(fused_kernel, cudaFuncAttributeMaxDynamicSharedMemorySize,
                         TILE_SMEM);

    setup_kernel<<<1, 256>>>(lg, mg, mfc, mq, hg);
    fused_kernel<<<GRID, 128, TILE_SMEM>>>(x, y);
}